// round 4
// baseline (speedup 1.0000x reference)
#include <cuda_runtime.h>
#include <cstdint>

// Problem constants (match reference)
#define NN      100000
#define EE      3200000
#define GAMMA   0.1f

#define EDGE_CHUNKS   (EE / 4)                 // 800000 work items of 4 edges
#define DAMP_CHUNKS   ((NN + 3) / 4)           // 25000 work items of 4 nodes
#define TOTAL_CHUNKS  (EDGE_CHUNKS + DAMP_CHUNKS)

#define NBLOCKS  1184                          // 148 SMs * 8 CTAs -> single wave
#define NTHREADS 256

__device__ __forceinline__ void red_add_v2(float* addr, float a, float b) {
    asm volatile("red.global.add.v2.f32 [%0], {%1, %2};"
                 :: "l"(addr), "f"(a), "f"(b) : "memory");
}

__device__ __forceinline__ int4 ldcs_int4(const int4* p) {
    int4 r;
    asm volatile("ld.global.cs.v4.s32 {%0,%1,%2,%3}, [%4];"
                 : "=r"(r.x), "=r"(r.y), "=r"(r.z), "=r"(r.w) : "l"(p));
    return r;
}

// Persistent grid-stride kernel over zero-initialized out:
//   chunks [0, EDGE_CHUNKS):  4 edges each -> red.add message into out[dst]
//   chunks [EDGE_CHUNKS, +DAMP_CHUNKS): 4 nodes each -> red.add(-gamma*v)
// All contributions are atomic adds; no ordering needed.
__global__ void __launch_bounds__(NTHREADS) fused_edge_damp_kernel(
        const float* __restrict__ x,
        const float* __restrict__ v,
        const int*   __restrict__ src,
        const int*   __restrict__ dst,
        float* __restrict__ out) {
    const float2* __restrict__ x2 = reinterpret_cast<const float2*>(x);
    const int stride = NBLOCKS * NTHREADS;

    for (int t = blockIdx.x * NTHREADS + threadIdx.x; t < TOTAL_CHUNKS; t += stride) {
        if (t < EDGE_CHUNKS) {
            int4 s4 = ldcs_int4(reinterpret_cast<const int4*>(src) + t);
            int4 d4 = ldcs_int4(reinterpret_cast<const int4*>(dst) + t);

            int ss[4] = {s4.x, s4.y, s4.z, s4.w};
            int dd[4] = {d4.x, d4.y, d4.z, d4.w};

            float2 xs[4], xd[4];
#pragma unroll
            for (int k = 0; k < 4; k++) {
                xs[k] = __ldg(&x2[ss[k]]);
                xd[k] = __ldg(&x2[dd[k]]);
            }

#pragma unroll
            for (int k = 0; k < 4; k++) {
                float drx = xd[k].x - xs[k].x;
                float dry = xd[k].y - xs[k].y;
                float d2  = fmaf(drx, drx, dry * dry);
                // f = -C*P*(ab - R_C)/ab = 2*rsqrt(d2) - 2 ; zero for d2==0
                float f = (d2 > 0.0f) ? fmaf(2.0f, rsqrtf(d2), -2.0f) : 0.0f;
                red_add_v2(out + 2 * dd[k], f * drx, f * dry);
            }
        } else {
            int i4 = (t - EDGE_CHUNKS) * 4;
#pragma unroll
            for (int k = 0; k < 4; k++) {
                int i = i4 + k;
                if (i < NN) {
                    float2 vv = __ldg(&reinterpret_cast<const float2*>(v)[i]);
                    red_add_v2(out + 2 * i, -GAMMA * vv.x, -GAMMA * vv.y);
                }
            }
        }
    }
}

extern "C" void kernel_launch(void* const* d_in, const int* in_sizes, int n_in,
                              void* d_out, int out_size) {
    const float* x   = (const float*)d_in[0];
    const float* v   = (const float*)d_in[1];
    const int*   src = (const int*)d_in[2];
    const int*   dst = (const int*)d_in[3];
    float* out = (float*)d_out;

    // Zero the accumulator (graph-capturable memset node).
    cudaMemsetAsync(out, 0, (size_t)out_size * sizeof(float), 0);

    fused_edge_damp_kernel<<<NBLOCKS, NTHREADS>>>(x, v, src, dst, out);
}

// round 5
// speedup vs baseline: 1.0566x; 1.0566x over previous
#include <cuda_runtime.h>
#include <cstdint>

// Problem constants (match reference)
#define NN      100000
#define EE      3200000
#define GAMMA   0.1f

#define EDGE_THREADS (EE / 2)                   // 1,600,000 (2 edges each)
#define DAMP_THREADS ((NN + 1) / 2)             // 50,000 (2 nodes each)
#define TOTAL_THREADS (EDGE_THREADS + DAMP_THREADS)

__device__ __forceinline__ void red_add_v2(float* addr, float a, float b) {
    asm volatile("red.global.add.v2.f32 [%0], {%1, %2};"
                 :: "l"(addr), "f"(a), "f"(b) : "memory");
}

__device__ __forceinline__ int2 ldcs_int2(const int2* p) {
    int2 r;
    asm volatile("ld.global.cs.v2.s32 {%0,%1}, [%2];"
                 : "=r"(r.x), "=r"(r.y) : "l"(p));
    return r;
}

// Flat one-chunk-per-thread kernel over zero-initialized out:
//   threads [0, EDGE_THREADS):  2 edges each -> red.add message into out[dst]
//   threads [EDGE_THREADS, +DAMP_THREADS): 2 nodes -> red.add(-gamma*v)
// All contributions are atomic adds; no ordering needed.
__global__ void __launch_bounds__(256) fused_edge_damp_kernel(
        const float* __restrict__ x,
        const float* __restrict__ v,
        const int*   __restrict__ src,
        const int*   __restrict__ dst,
        float* __restrict__ out) {
    int t = blockIdx.x * blockDim.x + threadIdx.x;

    if (t < EDGE_THREADS) {
        const float2* __restrict__ x2 = reinterpret_cast<const float2*>(x);

        int2 s2 = ldcs_int2(reinterpret_cast<const int2*>(src) + t);
        int2 d2i = ldcs_int2(reinterpret_cast<const int2*>(dst) + t);

        int ss[2] = {s2.x, s2.y};
        int dd[2] = {d2i.x, d2i.y};

        float2 xs[2], xd[2];
#pragma unroll
        for (int k = 0; k < 2; k++) {
            xs[k] = __ldg(&x2[ss[k]]);
            xd[k] = __ldg(&x2[dd[k]]);
        }

#pragma unroll
        for (int k = 0; k < 2; k++) {
            float drx = xd[k].x - xs[k].x;
            float dry = xd[k].y - xs[k].y;
            float d2  = fmaf(drx, drx, dry * dry);
            // f = -C*P*(ab - R_C)/ab = 2*rsqrt(d2) - 2 ; zero for d2==0
            float f = (d2 > 0.0f) ? fmaf(2.0f, rsqrtf(d2), -2.0f) : 0.0f;
            red_add_v2(out + 2 * dd[k], f * drx, f * dry);
        }
    } else {
        int i2 = (t - EDGE_THREADS) * 2;
#pragma unroll
        for (int k = 0; k < 2; k++) {
            int i = i2 + k;
            if (i < NN) {
                float2 vv = __ldg(&reinterpret_cast<const float2*>(v)[i]);
                red_add_v2(out + 2 * i, -GAMMA * vv.x, -GAMMA * vv.y);
            }
        }
    }
}

extern "C" void kernel_launch(void* const* d_in, const int* in_sizes, int n_in,
                              void* d_out, int out_size) {
    const float* x   = (const float*)d_in[0];
    const float* v   = (const float*)d_in[1];
    const int*   src = (const int*)d_in[2];
    const int*   dst = (const int*)d_in[3];
    float* out = (float*)d_out;

    // Zero the accumulator (graph-capturable memset node).
    cudaMemsetAsync(out, 0, (size_t)out_size * sizeof(float), 0);

    int threads = 256;
    int blocks = (TOTAL_THREADS + threads - 1) / threads;  // 6446
    fused_edge_damp_kernel<<<blocks, threads>>>(x, v, src, dst, out);
}